// round 17
// baseline (speedup 1.0000x reference)
#include <cuda_runtime.h>
#include <cuda_fp16.h>
#include <math.h>
#include <cstdint>

#define BB   8
#define CI   64
#define CO   64
#define HH   128
#define WW   128
#define CTXC 16
#define FF   576
#define HWSZ (HH*WW)

// conv smem (bytes) — 48B stride per 16-ch slice (32B payload + 16B pad)
#define CSTRIDE 48
#define XROWB  (132*CSTRIDE)          // 6336 B per halo row
#define XBYTES (4*XROWB)              // 25344 (2-row band + 2 halo)
#define WBYTES (9*64*CSTRIDE)         // 27648
#define SMEMB  (2*XBYTES + 2*WBYTES)  // 105984 -> 2 CTAs/SM
#define NT     256

// ---- device scratch ----
__device__ float g_meanx[BB * CI];
__device__ float g_rowsum[HH * BB * CI];   // [y][b*64+c]
__device__ __align__(16) __half g_wt[(size_t)BB * 9 * CO * CI];   // [b][tap][o][c], x256
__device__ __align__(16) __half g_xh[(size_t)BB * HH * WW * CI];  // [b][y][x][c]

__device__ __forceinline__ void cp_async16z(uint32_t dst, const void* src, bool pred) {
    int sz = pred ? 16 : 0;
    asm volatile("cp.async.cg.shared.global [%0], [%1], 16, %2;"
                 :: "r"(dst), "l"(src), "r"(sz));
}
__device__ __forceinline__ void cp_commit() { asm volatile("cp.async.commit_group;"); }

// ======= kernel 1: transpose x -> fp16 [b][y][x][c], plus per-row channel sums =======
__global__ void k_xpose(const float* __restrict__ x) {
    __shared__ __half stage[128 * 66];
    __shared__ float psum[64 * 2];
    int t = threadIdx.x;
    int y = blockIdx.x, b = blockIdx.y;
    int xcol = t & 127, chalf = t >> 7;

#pragma unroll
    for (int c0 = 0; c0 < 64; c0 += 2) {
        int c = c0 + chalf;
        float v = x[(((size_t)(b * 64 + c)) * HH + y) * WW + xcol];
        stage[xcol * 66 + c] = __float2half_rn(v);
    }
    __syncthreads();
    if (t < 128) {
        int c = t & 63, h = t >> 6;
        float s = 0.f;
#pragma unroll 8
        for (int xx = 64 * h; xx < 64 * h + 64; xx++)
            s += __half2float(stage[xx * 66 + c]);
        psum[c * 2 + h] = s;
    }
    __syncthreads();
    if (t < 64)
        g_rowsum[y * (BB * CI) + b * 64 + t] = psum[t * 2] + psum[t * 2 + 1];

    int w = t >> 5, lane = t & 31;
    uint32_t* dst = (uint32_t*)g_xh + (((size_t)b * HH + y) * WW) * 32;
#pragma unroll
    for (int k = 0; k < 16; k++) {
        int xx = w + 8 * k;
        uint32_t v = *(const uint32_t*)&stage[xx * 66 + 2 * lane];
        dst[(size_t)xx * 32 + lane] = v;
    }
}

// ======= kernel 1b: reduce row sums -> mean (coalesced) =======
__global__ void k_red() {
    int t = threadIdx.x;     // 0..511 = b*64+c
    float s = 0.f;
#pragma unroll 8
    for (int y = 0; y < HH; y++) s += g_rowsum[y * (BB * CI) + t];
    g_meanx[t] = s * (1.f / (float)HWSZ);
}

// == kernel 2: generate kernels, center, fold value_w -> g_wt (fp16, x256) ==
__global__ void k_gen(const float* __restrict__ ctx_w, const float* __restrict__ ctx_b,
                      const float* __restrict__ kg_w, const float* __restrict__ kg_b,
                      const float* __restrict__ gamma, const float* __restrict__ value_w) {
    int bo = blockIdx.x;
    int b = bo >> 6, o = bo & 63;
    __shared__ float ctx_s[CTXC];
    __shared__ float kern_s[FF];
    __shared__ float vw_s[CI * CI];
    __shared__ float red[6];
    int t = threadIdx.x;
    if (t < CTXC) {
        float s = ctx_b[t];
#pragma unroll 8
        for (int c = 0; c < CI; c++) s += ctx_w[t * CI + c] * g_meanx[b * CI + c];
        ctx_s[t] = s;
    }
    for (int i = t; i < CI * CI; i += 192) vw_s[i] = value_w[i];
    __syncthreads();

    float part = 0.f;
#pragma unroll
    for (int i = 0; i < 3; i++) {
        int f = t + 192 * i;
        const float4* wr = (const float4*)(kg_w + (size_t)(o * FF + f) * 16);
        float s = kg_b[o * FF + f];
#pragma unroll
        for (int jj = 0; jj < 4; jj++) {
            float4 w = wr[jj];
            s += ctx_s[4 * jj + 0] * w.x + ctx_s[4 * jj + 1] * w.y
               + ctx_s[4 * jj + 2] * w.z + ctx_s[4 * jj + 3] * w.w;
        }
        s = tanhf(s);
        kern_s[f] = s;
        part += s;
    }
#pragma unroll
    for (int off = 16; off; off >>= 1) part += __shfl_xor_sync(0xffffffffu, part, off);
    if ((t & 31) == 0) red[t >> 5] = part;
    __syncthreads();
    float total = red[0] + red[1] + red[2] + red[3] + red[4] + red[5];
    float lam = 1.f / (1.f + __expf(-gamma[o]));
    float sub = lam * total * (1.f / (float)FF);

#pragma unroll
    for (int i = 0; i < 3; i++) {
        int f = t + 192 * i;
        int cin = f / 9, kk = f % 9;
        float s = 0.f;
#pragma unroll 16
        for (int cp = 0; cp < CI; cp++)
            s += (kern_s[cp * 9 + kk] - sub) * vw_s[cp * CI + cin];
        g_wt[(((size_t)b * 9 + kk) * CO + o) * CI + cin] = __float2half_rn(s * 256.f);
    }
}

// ======== kernel 3: conv via mma.sync m16n8k16 fp16 + ldmatrix B ========
// CTA 256 thr (8 warps), 2 CTAs/SM. warp = (oHalf = wid&1, rowi = (wid>>1)&1,
// colHalf = wid>>2): 32 o x 1 row x 64 cols per warp. Band = 2 rows, halo 4.
__device__ __forceinline__ void load_chunk(uint32_t sb, int b, int kc, int y0,
                                           int buf, int t) {
    uint32_t xd = sb + (uint32_t)buf * XBYTES;
    const char* xb = (const char*)g_xh;
#pragma unroll
    for (int i = 0; i < 5; i++) {
        int e = t + NT * i;            // 0..1039 (4*130*2)
        if (e < 1040) {
            int p = e >> 1, hh = e & 1;
            int r = p / 130, j = p - r * 130;
            int gy = y0 - 1 + r, gx = j - 1;
            bool ok = (gy >= 0) && (gy < HH) && (gx >= 0) && (gx < WW);
            const char* src = xb + ((((size_t)b * HH + (ok ? gy : 0)) * WW
                                     + (ok ? gx : 0)) * 64 + kc * 16) * 2 + hh * 16;
            cp_async16z(xd + (uint32_t)(r * XROWB + j * CSTRIDE + hh * 16), src, ok);
        }
    }
    uint32_t wd = sb + 2u * XBYTES + (uint32_t)buf * WBYTES;
    const char* wb = (const char*)g_wt + ((size_t)b * 9 * CO * CI + kc * 16) * 2;
#pragma unroll
    for (int i = 0; i < 5; i++) {
        int e = t + NT * i;            // 0..1151 (9*64*2)
        if (e < 1152) {
            int tap = e >> 7, rem = e & 127;
            int o = rem >> 1, hh = rem & 1;
            const char* src = wb + ((size_t)(tap * CO + o)) * (CI * 2) + hh * 16;
            cp_async16z(wd + (uint32_t)((tap * 64 + o) * CSTRIDE + hh * 16), src, true);
        }
    }
}

__global__ void __launch_bounds__(NT, 2)
k_conv(const float* __restrict__ bias, float* __restrict__ out) {
    extern __shared__ __align__(16) char smem[];
    uint32_t sb = (uint32_t)__cvta_generic_to_shared(smem);
    int t = threadIdx.x;
    int lane = t & 31, wid = t >> 5;
    int oHalf = wid & 1, rowi = (wid >> 1) & 1, colHalf = wid >> 2;
    int o_base = oHalf * 32;
    int col_base = colHalf * 64;
    int l4 = lane & 3, l2 = lane >> 2;
    int b = blockIdx.y, band = blockIdx.x;
    int y0 = band * 2;
    int y = y0 + rowi;

    // ldmatrix lane->row mapping: tile = lane>>3, row-in-tile = lane&7
    int tile = lane >> 3, rr = lane & 7;
    int nn = ((tile >> 1) << 3) + rr;
    uint32_t bxoff = (uint32_t)((col_base + nn) * CSTRIDE + (tile & 1) * 16);

    float acc[2][8][4];
#pragma unroll
    for (int s = 0; s < 2; s++)
#pragma unroll
        for (int n = 0; n < 8; n++)
#pragma unroll
            for (int i = 0; i < 4; i++) acc[s][n][i] = 0.f;

    load_chunk(sb, b, 0, y0, 0, t);
    cp_commit();

    for (int kc = 0; kc < 4; kc++) {
        if (kc < 3) {
            load_chunk(sb, b, kc + 1, y0, (kc + 1) & 1, t);
            cp_commit();
            asm volatile("cp.async.wait_group 1;");
        } else {
            asm volatile("cp.async.wait_group 0;");
        }
        __syncthreads();

        uint32_t xsb = sb + (uint32_t)(kc & 1) * XBYTES;
        const uint32_t* ws = (const uint32_t*)(smem + 2 * XBYTES + (kc & 1) * WBYTES);

        for (int tap = 0; tap < 9; tap++) {
            int kh = tap / 3, kw = tap % 3;
            // A fragments for both 16-o strips (stride-12 words, conflict-free)
            const uint32_t* wp0 = ws + (tap * 64 + o_base + l2) * 12 + l4;
            const uint32_t* wp1 = wp0 + 16 * 12;
            uint32_t a00 = wp0[0],  a01 = wp0[96],  a02 = wp0[4],  a03 = wp0[100];
            uint32_t a10 = wp1[0],  a11 = wp1[96],  a12 = wp1[4],  a13 = wp1[100];
            uint32_t rowb = xsb + (uint32_t)((rowi + kh) * XROWB + kw * CSTRIDE) + bxoff;
#pragma unroll
            for (int g = 0; g < 4; g++) {
                uint32_t addr = rowb + (uint32_t)(g * 16 * CSTRIDE);
                uint32_t b0, b1, b2, b3;
                asm volatile(
                    "ldmatrix.sync.aligned.m8n8.x4.shared.b16 {%0,%1,%2,%3}, [%4];"
                    : "=r"(b0), "=r"(b1), "=r"(b2), "=r"(b3) : "r"(addr));
                asm volatile(
                    "mma.sync.aligned.m16n8k16.row.col.f32.f16.f16.f32 "
                    "{%0,%1,%2,%3}, {%4,%5,%6,%7}, {%8,%9}, {%0,%1,%2,%3};"
                    : "+f"(acc[0][2*g][0]), "+f"(acc[0][2*g][1]),
                      "+f"(acc[0][2*g][2]), "+f"(acc[0][2*g][3])
                    : "r"(a00), "r"(a01), "r"(a02), "r"(a03), "r"(b0), "r"(b1));
                asm volatile(
                    "mma.sync.aligned.m16n8k16.row.col.f32.f16.f16.f32 "
                    "{%0,%1,%2,%3}, {%4,%5,%6,%7}, {%8,%9}, {%0,%1,%2,%3};"
                    : "+f"(acc[0][2*g+1][0]), "+f"(acc[0][2*g+1][1]),
                      "+f"(acc[0][2*g+1][2]), "+f"(acc[0][2*g+1][3])
                    : "r"(a00), "r"(a01), "r"(a02), "r"(a03), "r"(b2), "r"(b3));
                asm volatile(
                    "mma.sync.aligned.m16n8k16.row.col.f32.f16.f16.f32 "
                    "{%0,%1,%2,%3}, {%4,%5,%6,%7}, {%8,%9}, {%0,%1,%2,%3};"
                    : "+f"(acc[1][2*g][0]), "+f"(acc[1][2*g][1]),
                      "+f"(acc[1][2*g][2]), "+f"(acc[1][2*g][3])
                    : "r"(a10), "r"(a11), "r"(a12), "r"(a13), "r"(b0), "r"(b1));
                asm volatile(
                    "mma.sync.aligned.m16n8k16.row.col.f32.f16.f16.f32 "
                    "{%0,%1,%2,%3}, {%4,%5,%6,%7}, {%8,%9}, {%0,%1,%2,%3};"
                    : "+f"(acc[1][2*g+1][0]), "+f"(acc[1][2*g+1][1]),
                      "+f"(acc[1][2*g+1][2]), "+f"(acc[1][2*g+1][3])
                    : "r"(a10), "r"(a11), "r"(a12), "r"(a13), "r"(b2), "r"(b3));
            }
        }
        __syncthreads();
    }

    // ---- epilogue: un-scale (W was x256), bias, relu ----
    const float inv = 1.f / 256.f;
#pragma unroll
    for (int s = 0; s < 2; s++) {
        int o = o_base + s * 16 + l2;
        float bz0 = bias[o], bz1 = bias[o + 8];
        float* r0 = out + (((size_t)b * CO + o) * HH + y) * WW + col_base;
        float* r1 = r0 + (size_t)8 * HH * WW;
#pragma unroll
        for (int nt = 0; nt < 8; nt++) {
            int col = nt * 8 + l4 * 2;
            float2 v0, v1;
            float u0 = fmaf(acc[s][nt][0], inv, bz0), u1 = fmaf(acc[s][nt][1], inv, bz0);
            float u2 = fmaf(acc[s][nt][2], inv, bz1), u3 = fmaf(acc[s][nt][3], inv, bz1);
            v0.x = u0 > 0.f ? u0 : 0.f;
            v0.y = u1 > 0.f ? u1 : 0.f;
            v1.x = u2 > 0.f ? u2 : 0.f;
            v1.y = u3 > 0.f ? u3 : 0.f;
            *(float2*)(r0 + col) = v0;
            *(float2*)(r1 + col) = v1;
        }
    }
}

// ================================ launch ================================
extern "C" void kernel_launch(void* const* d_in, const int* in_sizes, int n_in,
                              void* d_out, int out_size) {
    const float* x       = (const float*)d_in[0];
    const float* ctx_w   = (const float*)d_in[1];
    const float* ctx_b   = (const float*)d_in[2];
    const float* kg_w    = (const float*)d_in[3];
    const float* kg_b    = (const float*)d_in[4];
    const float* gamma   = (const float*)d_in[5];
    const float* bias    = (const float*)d_in[6];
    const float* value_w = (const float*)d_in[7];
    float* out = (float*)d_out;

    static int smem_set = 0;
    if (!smem_set) {
        cudaFuncSetAttribute(k_conv, cudaFuncAttributeMaxDynamicSharedMemorySize, SMEMB);
        smem_set = 1;
    }

    dim3 gx(HH, BB);
    k_xpose<<<gx, 256>>>(x);
    k_red<<<1, BB * CI>>>();
    k_gen<<<BB * CO, 192>>>(ctx_w, ctx_b, kg_w, kg_b, gamma, value_w);
    dim3 grid(HH / 2, BB);   // (row band of 2, batch)
    k_conv<<<grid, NT, SMEMB>>>(bias, out);
}